// round 3
// baseline (speedup 1.0000x reference)
#include <cuda_runtime.h>

// ---------------------------------------------------------------------------
// Sinkhorn (Wasserstein) loss, B=16, N=M=1024, D=32, EPS=1e-3, THRESH=0.1
//
// u_new_i = EPS*log_mu - max_j(v_j - C_ij) - EPS*ln(sum_j exp((x_j - max)/EPS))
// v_new_j = EPS*log_nu - max_i(u_new_i - C_ij) - EPS*ln(...)
// err     = (1/16) * sum_{b,i} |u_new - u|;  stop after the iteration where
//           err < 0.1 (that iteration's u AND v updates are applied).
// cost    = (1/16) * sum_{b,i,j} exp((u_i+v_j-C_ij)/EPS) * C_ij
// ---------------------------------------------------------------------------

#define BB    16
#define NN    1024
#define ROWS  (BB * NN)            // 16384 rows per pass
#define NBLK  148
#define NTHR  256
#define NWARP 8
#define TOTW  (NBLK * NWARP)       // 1184 warps

// EPS * log(1/1024 + 1e-8)
#define K_EPSLOGMU  (-6.9314616e-3f)
// log2(e) / EPS
#define K_L2E_EPS   (1442.6950409f)
// exp cutoff: (x - max) >= -0.032  ->  relative term >= 2^-46 (negligible below)
#define K_CUT       (-0.032f)

__device__ float g_C [16u * 1024u * 1024u];   // C[b][i][j]
__device__ float g_CT[16u * 1024u * 1024u];   // C[b][j][i]
__device__ float g_u[ROWS];
__device__ float g_v[ROWS];
__device__ float g_errpart[NBLK];
__device__ float g_costpart[NBLK];
__device__ unsigned g_count;
__device__ unsigned g_release;

// ---------------------------------------------------------------------------
__global__ void init_kernel() {
    int i = blockIdx.x * blockDim.x + threadIdx.x;
    if (i < ROWS) { g_u[i] = 0.0f; g_v[i] = 0.0f; }
    if (i == 0)   { g_count = 0u; g_release = 0u; }
}

// ---------------------------------------------------------------------------
// C[b][i][j] = sum_d (x[b][i][d] - y[b][j][d])^2 ; 32x32 output tile per block
__global__ void compute_C_kernel(const float* __restrict__ X,
                                 const float* __restrict__ Y) {
    __shared__ float xs[32][33];
    __shared__ float ys[32][33];
    int b  = blockIdx.z;
    int i0 = blockIdx.y * 32;
    int j0 = blockIdx.x * 32;
    int tid = threadIdx.x;

    const float* xp = X + ((size_t)(b * NN + i0)) * 32;   // 1024 contiguous floats
    const float* yp = Y + ((size_t)(b * NN + j0)) * 32;
    for (int idx = tid; idx < 1024; idx += NTHR) {
        xs[idx >> 5][idx & 31] = xp[idx];
        ys[idx >> 5][idx & 31] = yp[idx];
    }
    __syncthreads();

    int tx = tid & 31;        // j within tile
    int ty = tid >> 5;        // i base (0..7), computes i = ty, ty+8, ty+16, ty+24
    float a0 = 0.f, a1 = 0.f, a2 = 0.f, a3 = 0.f;
#pragma unroll
    for (int d = 0; d < 32; d++) {
        float yv = ys[tx][d];
        float d0 = xs[ty][d]      - yv; a0 += d0 * d0;
        float d1 = xs[ty +  8][d] - yv; a1 += d1 * d1;
        float d2 = xs[ty + 16][d] - yv; a2 += d2 * d2;
        float d3 = xs[ty + 24][d] - yv; a3 += d3 * d3;
    }
    size_t base = ((size_t)b << 20);
    g_C[base + ((size_t)(i0 + ty)      << 10) + j0 + tx] = a0;
    g_C[base + ((size_t)(i0 + ty +  8) << 10) + j0 + tx] = a1;
    g_C[base + ((size_t)(i0 + ty + 16) << 10) + j0 + tx] = a2;
    g_C[base + ((size_t)(i0 + ty + 24) << 10) + j0 + tx] = a3;
}

// ---------------------------------------------------------------------------
__global__ void transpose_kernel() {
    __shared__ float tile[32][33];
    int b  = blockIdx.z;
    int i0 = blockIdx.y * 32;
    int j0 = blockIdx.x * 32;
    int x = threadIdx.x;
    int y = threadIdx.y;
    size_t base = ((size_t)b << 20);
#pragma unroll
    for (int k = 0; k < 32; k += 8)
        tile[y + k][x] = g_C[base + ((size_t)(i0 + y + k) << 10) + j0 + x];
    __syncthreads();
#pragma unroll
    for (int k = 0; k < 32; k += 8)
        g_CT[base + ((size_t)(j0 + y + k) << 10) + i0 + x] = tile[x][y + k];
}

// ---------------------------------------------------------------------------
// Hand-rolled grid barrier. Safe: 148 blocks <= SM count, launch_bounds(256,1)
// guarantees co-residency. g_count/g_release reset by init_kernel each launch.
__device__ __forceinline__ void grid_barrier(unsigned target) {
    __syncthreads();
    if (threadIdx.x == 0) {
        __threadfence();
        if (atomicAdd(&g_count, 1u) == NBLK - 1u) {
            g_count = 0u;
            __threadfence();
            atomicAdd(&g_release, 1u);
        } else {
            while (*((volatile unsigned*)&g_release) < target) { __nanosleep(64); }
        }
        __threadfence();
    }
    __syncthreads();
}

// ---------------------------------------------------------------------------
// One logsumexp sweep: warp per row, row = 1024 elements, lane holds 8 float4.
// vin/vout are cross-SM shared -> read with __ldcg (L1 not coherent in-launch).
__device__ __forceinline__ float sk_pass(const float* __restrict__ Cmat,
                                         const float* __restrict__ vin,
                                         float*       __restrict__ vout,
                                         int gw, int lane, bool do_err) {
    float errloc = 0.0f;
    for (int row = gw; row < ROWS; row += TOTW) {
        const float4* cr = reinterpret_cast<const float4*>(Cmat) + ((size_t)row << 8);
        const float4* vr = reinterpret_cast<const float4*>(vin)  + ((size_t)(row >> 10) << 8);
        float4 Xv[8];
        float m = -3.0e38f;
#pragma unroll
        for (int k = 0; k < 8; k++) {
            float4 c = cr[k * 32 + lane];
            float4 v = __ldcg(&vr[k * 32 + lane]);
            float4 x;
            x.x = v.x - c.x; x.y = v.y - c.y; x.z = v.z - c.z; x.w = v.w - c.w;
            Xv[k] = x;
            m = fmaxf(m, fmaxf(fmaxf(x.x, x.y), fmaxf(x.z, x.w)));
        }
        float lm = m;
#pragma unroll
        for (int off = 16; off; off >>= 1)
            m = fmaxf(m, __shfl_xor_sync(0xffffffffu, m, off));
        float s = 0.0f;
        if (lm >= m + K_CUT) {           // this lane may hold a contributing term
#pragma unroll
            for (int k = 0; k < 8; k++) {
                float t;
                t = Xv[k].x - m; if (t >= K_CUT) s += exp2f(t * K_L2E_EPS);
                t = Xv[k].y - m; if (t >= K_CUT) s += exp2f(t * K_L2E_EPS);
                t = Xv[k].z - m; if (t >= K_CUT) s += exp2f(t * K_L2E_EPS);
                t = Xv[k].w - m; if (t >= K_CUT) s += exp2f(t * K_L2E_EPS);
            }
        }
#pragma unroll
        for (int off = 16; off; off >>= 1)
            s += __shfl_xor_sync(0xffffffffu, s, off);
        if (lane == 0) {
            float nv = K_EPSLOGMU - m - 1e-3f * __logf(s);   // s >= 1 always
            if (do_err) errloc += fabsf(nv - __ldcg(&vout[row]));
            vout[row] = nv;
        }
    }
    return errloc;
}

// ---------------------------------------------------------------------------
__global__ __launch_bounds__(NTHR, 1) void sinkhorn_kernel(float* __restrict__ out) {
    __shared__ float s_red[NWARP];
    __shared__ float s_bcast;
    int tid  = threadIdx.x;
    int lane = tid & 31;
    int warp = tid >> 5;
    int gw   = blockIdx.x * NWARP + warp;
    unsigned bar = 0;

    for (int iter = 0; iter < 100; iter++) {
        // ---- u update (row logsumexp over C) + err ----
        float e = sk_pass(g_C, g_v, g_u, gw, lane, true);
        if (lane == 0) s_red[warp] = e;
        __syncthreads();
        if (tid == 0) {
            float t = 0.f;
            for (int w = 0; w < NWARP; w++) t += s_red[w];
            g_errpart[blockIdx.x] = t;
        }
        grid_barrier(++bar);
        // err parts are final now; read them BEFORE the next barrier so the
        // next iteration's overwrite can't race this read.
        if (tid == 0) {
            float t = 0.f;
            for (int b = 0; b < NBLK; b++) t += __ldcg(&g_errpart[b]);
            s_bcast = t;
        }
        __syncthreads();
        float errtot = s_bcast;
        // ---- v update (row logsumexp over C^T, uses fresh u) ----
        sk_pass(g_CT, g_u, g_v, gw, lane, false);
        grid_barrier(++bar);
        // Triggering iteration's updates ARE applied (matches reference).
        if (errtot * (1.0f / 16.0f) < 0.1f) break;
    }

    // ---- final cost: sum exp((u+v-C)/eps) * C ----
    float cacc = 0.0f;
    for (int row = gw; row < ROWS; row += TOTW) {
        float ui = __ldcg(&g_u[row]);
        const float4* cr = reinterpret_cast<const float4*>(g_C) + ((size_t)row << 8);
        const float4* vr = reinterpret_cast<const float4*>(g_v) + ((size_t)(row >> 10) << 8);
#pragma unroll
        for (int k = 0; k < 8; k++) {
            float4 c = cr[k * 32 + lane];
            float4 v = __ldcg(&vr[k * 32 + lane]);
            float t;
            t = ui + v.x - c.x; if (t > -0.04f) cacc += exp2f(t * K_L2E_EPS) * c.x;
            t = ui + v.y - c.y; if (t > -0.04f) cacc += exp2f(t * K_L2E_EPS) * c.y;
            t = ui + v.z - c.z; if (t > -0.04f) cacc += exp2f(t * K_L2E_EPS) * c.z;
            t = ui + v.w - c.w; if (t > -0.04f) cacc += exp2f(t * K_L2E_EPS) * c.w;
        }
    }
#pragma unroll
    for (int off = 16; off; off >>= 1)
        cacc += __shfl_xor_sync(0xffffffffu, cacc, off);
    if (lane == 0) s_red[warp] = cacc;
    __syncthreads();
    if (tid == 0) {
        float t = 0.f;
        for (int w = 0; w < NWARP; w++) t += s_red[w];
        g_costpart[blockIdx.x] = t;
    }
    grid_barrier(++bar);
    if (blockIdx.x == 0 && tid == 0) {
        float t = 0.f;
        for (int b = 0; b < NBLK; b++) t += __ldcg(&g_costpart[b]);
        out[0] = t * (1.0f / 16.0f);
    }
}

// ---------------------------------------------------------------------------
extern "C" void kernel_launch(void* const* d_in, const int* in_sizes, int n_in,
                              void* d_out, int out_size) {
    const float* X = (const float*)d_in[0];   // output [16,1024,32]
    const float* Y = (const float*)d_in[1];   // labels [16,1024,32]

    init_kernel<<<64, 256>>>();

    dim3 cgrid(32, 32, 16);
    compute_C_kernel<<<cgrid, NTHR>>>(X, Y);

    dim3 tgrid(32, 32, 16);
    transpose_kernel<<<tgrid, dim3(32, 8)>>>();

    sinkhorn_kernel<<<NBLK, NTHR>>>((float*)d_out);
}

// round 4
// speedup vs baseline: 2.5289x; 2.5289x over previous
#include <cuda_runtime.h>

// ---------------------------------------------------------------------------
// Sinkhorn (Wasserstein) loss, B=16, N=M=1024, D=32, EPS=1e-3, THRESH=0.1
// Round 3: L2-resident design. Only C (64MB) is kept; the column pass is an
// online (m,s) scan over row-major C with per-block partials. u and v live in
// shared memory per block. 144 persistent blocks, 2 grid barriers / iter.
// ---------------------------------------------------------------------------

#define BB    16
#define NN    1024
#define NBLK  144            // 9 row-chunk blocks per batch * 16 batches
#define RPB   9              // blocks per batch
#define NTHR  512
#define NWARP 16
#define CHUNK 114            // rows per chunk (last chunk gets 1024-8*114=112)

// EPS * log(1/1024 + 1e-8)
#define K_EPSLOGMU  (-6.9314616e-3f)
// log2(e) / EPS
#define K_L2E_EPS   (1442.6950409f)
// exp cutoff: terms below 2^-46 of the max are dropped
#define K_CUT       (-0.032f)

__device__ float  g_C[16u * 1024u * 1024u];   // C[b][i][j]
__device__ float2 g_part[NBLK * 1024];        // (m,s) partial per (block, column)
__device__ float  g_errpart[NBLK];
__device__ float  g_costpart[NBLK];
__device__ unsigned g_count;
__device__ unsigned g_release;

// ---------------------------------------------------------------------------
__global__ void init_kernel() {
    if (blockIdx.x == 0 && threadIdx.x == 0) { g_count = 0u; g_release = 0u; }
}

// ---------------------------------------------------------------------------
// C[b][i][j] = sum_d (x[b][i][d] - y[b][j][d])^2 ; 32x32 output tile per block
__global__ void compute_C_kernel(const float* __restrict__ X,
                                 const float* __restrict__ Y) {
    __shared__ float xs[32][33];
    __shared__ float ys[32][33];
    int b  = blockIdx.z;
    int i0 = blockIdx.y * 32;
    int j0 = blockIdx.x * 32;
    int tid = threadIdx.x;

    const float* xp = X + ((size_t)(b * NN + i0)) * 32;
    const float* yp = Y + ((size_t)(b * NN + j0)) * 32;
    for (int idx = tid; idx < 1024; idx += 256) {
        xs[idx >> 5][idx & 31] = xp[idx];
        ys[idx >> 5][idx & 31] = yp[idx];
    }
    __syncthreads();

    int tx = tid & 31;
    int ty = tid >> 5;
    float a0 = 0.f, a1 = 0.f, a2 = 0.f, a3 = 0.f;
#pragma unroll
    for (int d = 0; d < 32; d++) {
        float yv = ys[tx][d];
        float d0 = xs[ty][d]      - yv; a0 += d0 * d0;
        float d1 = xs[ty +  8][d] - yv; a1 += d1 * d1;
        float d2 = xs[ty + 16][d] - yv; a2 += d2 * d2;
        float d3 = xs[ty + 24][d] - yv; a3 += d3 * d3;
    }
    size_t base = ((size_t)b << 20);
    g_C[base + ((size_t)(i0 + ty)      << 10) + j0 + tx] = a0;
    g_C[base + ((size_t)(i0 + ty +  8) << 10) + j0 + tx] = a1;
    g_C[base + ((size_t)(i0 + ty + 16) << 10) + j0 + tx] = a2;
    g_C[base + ((size_t)(i0 + ty + 24) << 10) + j0 + tx] = a3;
}

// ---------------------------------------------------------------------------
// Grid barrier. 144 blocks <= 148 SMs, launch_bounds(512,1) -> co-resident.
__device__ __forceinline__ void grid_barrier(unsigned target) {
    __syncthreads();
    if (threadIdx.x == 0) {
        __threadfence();
        if (atomicAdd(&g_count, 1u) == NBLK - 1u) {
            g_count = 0u;
            __threadfence();
            atomicAdd(&g_release, 1u);
        } else {
            while (*((volatile unsigned*)&g_release) < target) { }
        }
        __threadfence();
    }
    __syncthreads();
}

// online (m,s) update with a single new term x (weight 1)
#define VUP(mm, ss, xx) do {                                                  \
    float x_ = (xx);                                                          \
    if (x_ > (mm)) {                                                          \
        float d_ = (mm) - x_;                                                 \
        (ss) = (ss) * ((d_ >= K_CUT) ? exp2f(d_ * K_L2E_EPS) : 0.f) + 1.f;    \
        (mm) = x_;                                                            \
    } else {                                                                  \
        float d_ = x_ - (mm);                                                 \
        if (d_ >= K_CUT) (ss) += exp2f(d_ * K_L2E_EPS);                       \
    }                                                                         \
} while (0)

// ---------------------------------------------------------------------------
__global__ __launch_bounds__(NTHR, 1) void sinkhorn_kernel(float* __restrict__ out) {
    __shared__ __align__(16) float s_v[1024];
    __shared__ float s_u[CHUNK];
    __shared__ float s_red[NWARP];
    __shared__ float s_bcast;

    int tid  = threadIdx.x;
    int lane = tid & 31;
    int warp = tid >> 5;
    int b    = blockIdx.x / RPB;
    int r    = blockIdx.x % RPB;
    int row0 = r * CHUNK;
    int cnt  = (r == RPB - 1) ? (NN - row0) : CHUNK;
    const float* Cb = g_C + ((size_t)b << 20);
    const float4* sv4 = (const float4*)s_v;
    unsigned bar = 0;

    if (tid < CHUNK) s_u[tid] = 0.f;   // u0 = 0 (synced by first barrier below)

    for (int iter = 0; iter < 100; iter++) {
        // ---- combine v partials (from previous iteration) into smem ----
        if (iter == 0) {
            for (int j = tid; j < 1024; j += NTHR) s_v[j] = 0.f;
        } else {
            for (int j = tid; j < 1024; j += NTHR) {
                float M = -3.0e38f, S = 0.f;
#pragma unroll
                for (int rr = 0; rr < RPB; rr++) {
                    float2 p = __ldcg(&g_part[(b * RPB + rr) * 1024 + j]);
                    if (p.x > M) {
                        float d = M - p.x;
                        S = S * ((d >= K_CUT) ? exp2f(d * K_L2E_EPS) : 0.f) + p.y;
                        M = p.x;
                    } else {
                        float d = p.x - M;
                        if (d >= K_CUT) S += p.y * exp2f(d * K_L2E_EPS);
                    }
                }
                s_v[j] = K_EPSLOGMU - M - 1e-3f * __logf(S);
            }
        }
        __syncthreads();

        // ---- u pass: warp per row, row logsumexp of (v_j - C_ij) ----
        float e = 0.f;
        for (int idx = warp; idx < cnt; idx += NWARP) {
            const float4* cr = (const float4*)(Cb + ((size_t)(row0 + idx) << 10));
            float4 Xv[8];
            float m = -3.0e38f;
#pragma unroll
            for (int k = 0; k < 8; k++) {
                float4 c = cr[k * 32 + lane];
                float4 v = sv4[k * 32 + lane];
                float4 x;
                x.x = v.x - c.x; x.y = v.y - c.y; x.z = v.z - c.z; x.w = v.w - c.w;
                Xv[k] = x;
                m = fmaxf(m, fmaxf(fmaxf(x.x, x.y), fmaxf(x.z, x.w)));
            }
            float lm = m;
#pragma unroll
            for (int off = 16; off; off >>= 1)
                m = fmaxf(m, __shfl_xor_sync(0xffffffffu, m, off));
            float s = 0.f;
            if (lm >= m + K_CUT) {
#pragma unroll
                for (int k = 0; k < 8; k++) {
                    float t;
                    t = Xv[k].x - m; if (t >= K_CUT) s += exp2f(t * K_L2E_EPS);
                    t = Xv[k].y - m; if (t >= K_CUT) s += exp2f(t * K_L2E_EPS);
                    t = Xv[k].z - m; if (t >= K_CUT) s += exp2f(t * K_L2E_EPS);
                    t = Xv[k].w - m; if (t >= K_CUT) s += exp2f(t * K_L2E_EPS);
                }
            }
#pragma unroll
            for (int off = 16; off; off >>= 1)
                s += __shfl_xor_sync(0xffffffffu, s, off);
            if (lane == 0) {
                float nv = K_EPSLOGMU - m - 1e-3f * __logf(s);
                e += fabsf(nv - s_u[idx]);
                s_u[idx] = nv;
            }
        }
        if (lane == 0) s_red[warp] = e;
        __syncthreads();
        if (warp == 0) {
            float t2 = (lane < NWARP) ? s_red[lane] : 0.f;
#pragma unroll
            for (int off = 16; off; off >>= 1)
                t2 += __shfl_xor_sync(0xffffffffu, t2, off);
            if (lane == 0) g_errpart[blockIdx.x] = t2;
        }
        grid_barrier(++bar);              // barrier A: u + err parts complete

        // total err (read between barriers; deterministic fixed order)
        if (warp == 0) {
            float t2 = 0.f;
            for (int i = lane; i < NBLK; i += 32) t2 += __ldcg(&g_errpart[i]);
#pragma unroll
            for (int off = 16; off; off >>= 1)
                t2 += __shfl_xor_sync(0xffffffffu, t2, off);
            if (lane == 0) s_bcast = t2;
        }

        // ---- v pass: online column logsumexp of (u_i - C_ij); thread owns 2 cols
        {
            float m0 = -3.0e38f, s0 = 0.f, m1 = -3.0e38f, s1 = 0.f;
            const float2* cr2 = (const float2*)(Cb + ((size_t)row0 << 10));
            int idx = 0;
            for (; idx + 4 <= cnt; idx += 4) {
                float2 c0 = cr2[(size_t)(idx + 0) * 512 + tid];
                float2 c1 = cr2[(size_t)(idx + 1) * 512 + tid];
                float2 c2 = cr2[(size_t)(idx + 2) * 512 + tid];
                float2 c3 = cr2[(size_t)(idx + 3) * 512 + tid];
                float u0 = s_u[idx], u1 = s_u[idx + 1], u2 = s_u[idx + 2], u3 = s_u[idx + 3];
                VUP(m0, s0, u0 - c0.x); VUP(m1, s1, u0 - c0.y);
                VUP(m0, s0, u1 - c1.x); VUP(m1, s1, u1 - c1.y);
                VUP(m0, s0, u2 - c2.x); VUP(m1, s1, u2 - c2.y);
                VUP(m0, s0, u3 - c3.x); VUP(m1, s1, u3 - c3.y);
            }
            for (; idx < cnt; idx++) {
                float2 c = cr2[(size_t)idx * 512 + tid];
                float u0 = s_u[idx];
                VUP(m0, s0, u0 - c.x); VUP(m1, s1, u0 - c.y);
            }
            // columns (2*tid, 2*tid+1) -> one float4 store
            ((float4*)g_part)[blockIdx.x * 512 + tid] = make_float4(m0, s0, m1, s1);
        }
        grid_barrier(++bar);              // barrier B: v partials complete

        if (s_bcast * (1.0f / 16.0f) < 0.1f) break;
    }

    // ---- final v combine + transport cost ----
    for (int j = tid; j < 1024; j += NTHR) {
        float M = -3.0e38f, S = 0.f;
#pragma unroll
        for (int rr = 0; rr < RPB; rr++) {
            float2 p = __ldcg(&g_part[(b * RPB + rr) * 1024 + j]);
            if (p.x > M) {
                float d = M - p.x;
                S = S * ((d >= K_CUT) ? exp2f(d * K_L2E_EPS) : 0.f) + p.y;
                M = p.x;
            } else {
                float d = p.x - M;
                if (d >= K_CUT) S += p.y * exp2f(d * K_L2E_EPS);
            }
        }
        s_v[j] = K_EPSLOGMU - M - 1e-3f * __logf(S);
    }
    __syncthreads();

    float acc = 0.f;
    for (int idx = warp; idx < cnt; idx += NWARP) {
        float ui = s_u[idx];
        const float4* cr = (const float4*)(Cb + ((size_t)(row0 + idx) << 10));
#pragma unroll
        for (int k = 0; k < 8; k++) {
            float4 c = cr[k * 32 + lane];
            float4 v = sv4[k * 32 + lane];
            float t;
            t = ui + v.x - c.x; if (t > -0.04f) acc += exp2f(t * K_L2E_EPS) * c.x;
            t = ui + v.y - c.y; if (t > -0.04f) acc += exp2f(t * K_L2E_EPS) * c.y;
            t = ui + v.z - c.z; if (t > -0.04f) acc += exp2f(t * K_L2E_EPS) * c.z;
            t = ui + v.w - c.w; if (t > -0.04f) acc += exp2f(t * K_L2E_EPS) * c.w;
        }
    }
#pragma unroll
    for (int off = 16; off; off >>= 1)
        acc += __shfl_xor_sync(0xffffffffu, acc, off);
    if (lane == 0) s_red[warp] = acc;
    __syncthreads();
    if (warp == 0) {
        float t2 = (lane < NWARP) ? s_red[lane] : 0.f;
#pragma unroll
        for (int off = 16; off; off >>= 1)
            t2 += __shfl_xor_sync(0xffffffffu, t2, off);
        if (lane == 0) g_costpart[blockIdx.x] = t2;
    }
    grid_barrier(++bar);

    if (blockIdx.x == 0 && warp == 0) {
        float t2 = 0.f;
        for (int i = lane; i < NBLK; i += 32) t2 += __ldcg(&g_costpart[i]);
#pragma unroll
        for (int off = 16; off; off >>= 1)
            t2 += __shfl_xor_sync(0xffffffffu, t2, off);
        if (lane == 0) out[0] = t2 * (1.0f / 16.0f);
    }
}

// ---------------------------------------------------------------------------
extern "C" void kernel_launch(void* const* d_in, const int* in_sizes, int n_in,
                              void* d_out, int out_size) {
    const float* X = (const float*)d_in[0];   // output [16,1024,32]
    const float* Y = (const float*)d_in[1];   // labels [16,1024,32]

    init_kernel<<<1, 32>>>();

    dim3 cgrid(32, 32, 16);
    compute_C_kernel<<<cgrid, 256>>>(X, Y);

    sinkhorn_kernel<<<NBLK, NTHR>>>((float*)d_out);
}

// round 5
// speedup vs baseline: 2.6346x; 1.0418x over previous
#include <cuda_runtime.h>

// ---------------------------------------------------------------------------
// Sinkhorn (Wasserstein) loss, B=16, N=M=1024, D=32, EPS=1e-3, THRESH=0.1
// Round 4: single grid barrier per iteration (parity double-buffered
// partials), nanosleep backoff spin, init merged into compute_C (2 launches
// per call -> deterministic ncu -s 5 alignment onto sinkhorn_kernel),
// v-pass unrolled x8 for load MLP.
// ---------------------------------------------------------------------------

#define BB    16
#define NN    1024
#define NBLK  144            // 9 row-chunk blocks per batch * 16 batches
#define RPB   9              // blocks per batch
#define NTHR  512
#define NWARP 16
#define CHUNK 114            // rows per chunk (last chunk gets 1024-8*114=112)

// EPS * log(1/1024 + 1e-8)
#define K_EPSLOGMU  (-6.9314616e-3f)
// log2(e) / EPS
#define K_L2E_EPS   (1442.6950409f)
// exp cutoff: terms below 2^-46 of the max are dropped
#define K_CUT       (-0.032f)

__device__ float  g_C[16u * 1024u * 1024u];     // C[b][i][j]
__device__ float2 g_part[2][NBLK * 1024];       // (m,s) per (block, column), parity-buffered
__device__ float  g_errpart[2][NBLK];
__device__ float  g_costpart[NBLK];
__device__ unsigned g_count;
__device__ unsigned g_release;

// ---------------------------------------------------------------------------
// C[b][i][j] = sum_d (x[b][i][d] - y[b][j][d])^2 ; 32x32 output tile per block
// Block (0,0,0) thread 0 also resets the grid-barrier counters for this launch.
__global__ void compute_C_kernel(const float* __restrict__ X,
                                 const float* __restrict__ Y) {
    __shared__ float xs[32][33];
    __shared__ float ys[32][33];
    int b  = blockIdx.z;
    int i0 = blockIdx.y * 32;
    int j0 = blockIdx.x * 32;
    int tid = threadIdx.x;

    if (blockIdx.x == 0 && blockIdx.y == 0 && blockIdx.z == 0 && tid == 0) {
        g_count = 0u; g_release = 0u;
    }

    const float* xp = X + ((size_t)(b * NN + i0)) * 32;
    const float* yp = Y + ((size_t)(b * NN + j0)) * 32;
    for (int idx = tid; idx < 1024; idx += 256) {
        xs[idx >> 5][idx & 31] = xp[idx];
        ys[idx >> 5][idx & 31] = yp[idx];
    }
    __syncthreads();

    int tx = tid & 31;
    int ty = tid >> 5;
    float a0 = 0.f, a1 = 0.f, a2 = 0.f, a3 = 0.f;
#pragma unroll
    for (int d = 0; d < 32; d++) {
        float yv = ys[tx][d];
        float d0 = xs[ty][d]      - yv; a0 += d0 * d0;
        float d1 = xs[ty +  8][d] - yv; a1 += d1 * d1;
        float d2 = xs[ty + 16][d] - yv; a2 += d2 * d2;
        float d3 = xs[ty + 24][d] - yv; a3 += d3 * d3;
    }
    size_t base = ((size_t)b << 20);
    g_C[base + ((size_t)(i0 + ty)      << 10) + j0 + tx] = a0;
    g_C[base + ((size_t)(i0 + ty +  8) << 10) + j0 + tx] = a1;
    g_C[base + ((size_t)(i0 + ty + 16) << 10) + j0 + tx] = a2;
    g_C[base + ((size_t)(i0 + ty + 24) << 10) + j0 + tx] = a3;
}

// ---------------------------------------------------------------------------
// Grid barrier. 144 blocks <= 148 SMs, launch_bounds(512,1) -> co-resident.
__device__ __forceinline__ void grid_barrier(unsigned target) {
    __syncthreads();
    if (threadIdx.x == 0) {
        __threadfence();
        if (atomicAdd(&g_count, 1u) == NBLK - 1u) {
            g_count = 0u;
            __threadfence();
            atomicAdd(&g_release, 1u);
        } else {
            while (*((volatile unsigned*)&g_release) < target) { __nanosleep(32); }
        }
        __threadfence();
    }
    __syncthreads();
}

// online (m,s) update with a single new term x (weight 1)
#define VUP(mm, ss, xx) do {                                                  \
    float x_ = (xx);                                                          \
    if (x_ > (mm)) {                                                          \
        float d_ = (mm) - x_;                                                 \
        (ss) = (ss) * ((d_ >= K_CUT) ? exp2f(d_ * K_L2E_EPS) : 0.f) + 1.f;    \
        (mm) = x_;                                                            \
    } else {                                                                  \
        float d_ = x_ - (mm);                                                 \
        if (d_ >= K_CUT) (ss) += exp2f(d_ * K_L2E_EPS);                       \
    }                                                                         \
} while (0)

// combine a partial (pm, ps) into running (M, S)
#define PCOMB(M, S, pm, ps) do {                                              \
    if ((pm) > (M)) {                                                         \
        float d_ = (M) - (pm);                                                \
        (S) = (S) * ((d_ >= K_CUT) ? exp2f(d_ * K_L2E_EPS) : 0.f) + (ps);     \
        (M) = (pm);                                                           \
    } else {                                                                  \
        float d_ = (pm) - (M);                                                \
        if (d_ >= K_CUT) (S) += (ps) * exp2f(d_ * K_L2E_EPS);                 \
    }                                                                         \
} while (0)

// ---------------------------------------------------------------------------
__global__ __launch_bounds__(NTHR, 1) void sinkhorn_kernel(float* __restrict__ out) {
    __shared__ __align__(16) float s_v[1024];
    __shared__ float s_u[CHUNK];
    __shared__ float s_red[NWARP];
    __shared__ float s_bcast;

    int tid  = threadIdx.x;
    int lane = tid & 31;
    int warp = tid >> 5;
    int b    = blockIdx.x / RPB;
    int r    = blockIdx.x % RPB;
    int row0 = r * CHUNK;
    int cnt  = (r == RPB - 1) ? (NN - row0) : CHUNK;
    const float* Cb = g_C + ((size_t)b << 20);
    const float4* sv4 = (const float4*)s_v;
    unsigned bar = 0;
    int p = 0;

    if (tid < CHUNK) s_u[tid] = 0.f;   // u0 = 0 (synced before first use below)

    for (int iter = 0; iter < 100; iter++) {
        p = iter & 1;
        // ---- combine v partials (written to buffer p^1 last iteration) ----
        if (iter == 0) {
            for (int j = tid; j < 1024; j += NTHR) s_v[j] = 0.f;
        } else {
            const float2* gp = g_part[p ^ 1];
            for (int j = tid; j < 1024; j += NTHR) {
                float M = -3.0e38f, S = 0.f;
#pragma unroll
                for (int rr = 0; rr < RPB; rr++) {
                    float2 q = __ldcg(&gp[(b * RPB + rr) * 1024 + j]);
                    PCOMB(M, S, q.x, q.y);
                }
                s_v[j] = K_EPSLOGMU - M - 1e-3f * __logf(S);
            }
        }
        __syncthreads();

        // ---- u pass: warp per row, row logsumexp of (v_j - C_ij) ----
        float e = 0.f;
        for (int idx = warp; idx < cnt; idx += NWARP) {
            const float4* cr = (const float4*)(Cb + ((size_t)(row0 + idx) << 10));
            float4 Xv[8];
            float m = -3.0e38f;
#pragma unroll
            for (int k = 0; k < 8; k++) {
                float4 c = cr[k * 32 + lane];
                float4 v = sv4[k * 32 + lane];
                float4 x;
                x.x = v.x - c.x; x.y = v.y - c.y; x.z = v.z - c.z; x.w = v.w - c.w;
                Xv[k] = x;
                m = fmaxf(m, fmaxf(fmaxf(x.x, x.y), fmaxf(x.z, x.w)));
            }
            float lm = m;
#pragma unroll
            for (int off = 16; off; off >>= 1)
                m = fmaxf(m, __shfl_xor_sync(0xffffffffu, m, off));
            float s = 0.f;
            if (lm >= m + K_CUT) {
#pragma unroll
                for (int k = 0; k < 8; k++) {
                    float t;
                    t = Xv[k].x - m; if (t >= K_CUT) s += exp2f(t * K_L2E_EPS);
                    t = Xv[k].y - m; if (t >= K_CUT) s += exp2f(t * K_L2E_EPS);
                    t = Xv[k].z - m; if (t >= K_CUT) s += exp2f(t * K_L2E_EPS);
                    t = Xv[k].w - m; if (t >= K_CUT) s += exp2f(t * K_L2E_EPS);
                }
            }
#pragma unroll
            for (int off = 16; off; off >>= 1)
                s += __shfl_xor_sync(0xffffffffu, s, off);
            if (lane == 0) {
                float nv = K_EPSLOGMU - m - 1e-3f * __logf(s);
                e += fabsf(nv - s_u[idx]);
                s_u[idx] = nv;
            }
        }
        if (lane == 0) s_red[warp] = e;
        __syncthreads();                    // s_u complete + s_red ready
        if (warp == 0) {
            float t2 = (lane < NWARP) ? s_red[lane] : 0.f;
#pragma unroll
            for (int off = 16; off; off >>= 1)
                t2 += __shfl_xor_sync(0xffffffffu, t2, off);
            if (lane == 0) g_errpart[p][blockIdx.x] = t2;
        }

        // ---- v pass: online column logsumexp of (u_i - C_ij); thread owns 2 cols
        {
            float m0 = -3.0e38f, s0 = 0.f, m1 = -3.0e38f, s1 = 0.f;
            const float2* cr2 = (const float2*)(Cb + ((size_t)row0 << 10));
            int idx = 0;
            for (; idx + 8 <= cnt; idx += 8) {
                float2 c0 = cr2[(size_t)(idx + 0) * 512 + tid];
                float2 c1 = cr2[(size_t)(idx + 1) * 512 + tid];
                float2 c2 = cr2[(size_t)(idx + 2) * 512 + tid];
                float2 c3 = cr2[(size_t)(idx + 3) * 512 + tid];
                float2 c4 = cr2[(size_t)(idx + 4) * 512 + tid];
                float2 c5 = cr2[(size_t)(idx + 5) * 512 + tid];
                float2 c6 = cr2[(size_t)(idx + 6) * 512 + tid];
                float2 c7 = cr2[(size_t)(idx + 7) * 512 + tid];
                float u0 = s_u[idx], u1 = s_u[idx + 1], u2 = s_u[idx + 2], u3 = s_u[idx + 3];
                float u4 = s_u[idx + 4], u5 = s_u[idx + 5], u6 = s_u[idx + 6], u7 = s_u[idx + 7];
                VUP(m0, s0, u0 - c0.x); VUP(m1, s1, u0 - c0.y);
                VUP(m0, s0, u1 - c1.x); VUP(m1, s1, u1 - c1.y);
                VUP(m0, s0, u2 - c2.x); VUP(m1, s1, u2 - c2.y);
                VUP(m0, s0, u3 - c3.x); VUP(m1, s1, u3 - c3.y);
                VUP(m0, s0, u4 - c4.x); VUP(m1, s1, u4 - c4.y);
                VUP(m0, s0, u5 - c5.x); VUP(m1, s1, u5 - c5.y);
                VUP(m0, s0, u6 - c6.x); VUP(m1, s1, u6 - c6.y);
                VUP(m0, s0, u7 - c7.x); VUP(m1, s1, u7 - c7.y);
            }
            for (; idx < cnt; idx++) {
                float2 c = cr2[(size_t)idx * 512 + tid];
                float u0 = s_u[idx];
                VUP(m0, s0, u0 - c.x); VUP(m1, s1, u0 - c.y);
            }
            // columns (2*tid, 2*tid+1) -> one float4 store into buffer p
            ((float4*)g_part[p])[blockIdx.x * 512 + tid] = make_float4(m0, s0, m1, s1);
        }

        grid_barrier(++bar);   // ONE barrier: err parts + v partials all visible

        // total err (deterministic fixed-order sum; identical in every block)
        if (warp == 0) {
            float t2 = 0.f;
            for (int i = lane; i < NBLK; i += 32) t2 += __ldcg(&g_errpart[p][i]);
#pragma unroll
            for (int off = 16; off; off >>= 1)
                t2 += __shfl_xor_sync(0xffffffffu, t2, off);
            if (lane == 0) s_bcast = t2;
        }
        __syncthreads();
        if (s_bcast * (1.0f / 16.0f) < 0.1f) break;
    }

    // ---- final v combine (from buffer p) + transport cost ----
    {
        const float2* gp = g_part[p];
        for (int j = tid; j < 1024; j += NTHR) {
            float M = -3.0e38f, S = 0.f;
#pragma unroll
            for (int rr = 0; rr < RPB; rr++) {
                float2 q = __ldcg(&gp[(b * RPB + rr) * 1024 + j]);
                PCOMB(M, S, q.x, q.y);
            }
            s_v[j] = K_EPSLOGMU - M - 1e-3f * __logf(S);
        }
    }
    __syncthreads();

    float acc = 0.f;
    for (int idx = warp; idx < cnt; idx += NWARP) {
        float ui = s_u[idx];
        const float4* cr = (const float4*)(Cb + ((size_t)(row0 + idx) << 10));
#pragma unroll
        for (int k = 0; k < 8; k++) {
            float4 c = cr[k * 32 + lane];
            float4 v = sv4[k * 32 + lane];
            float t;
            t = ui + v.x - c.x; if (t > -0.04f) acc += exp2f(t * K_L2E_EPS) * c.x;
            t = ui + v.y - c.y; if (t > -0.04f) acc += exp2f(t * K_L2E_EPS) * c.y;
            t = ui + v.z - c.z; if (t > -0.04f) acc += exp2f(t * K_L2E_EPS) * c.z;
            t = ui + v.w - c.w; if (t > -0.04f) acc += exp2f(t * K_L2E_EPS) * c.w;
        }
    }
#pragma unroll
    for (int off = 16; off; off >>= 1)
        acc += __shfl_xor_sync(0xffffffffu, acc, off);
    if (lane == 0) s_red[warp] = acc;
    __syncthreads();
    if (warp == 0) {
        float t2 = (lane < NWARP) ? s_red[lane] : 0.f;
#pragma unroll
        for (int off = 16; off; off >>= 1)
            t2 += __shfl_xor_sync(0xffffffffu, t2, off);
        if (lane == 0) g_costpart[blockIdx.x] = t2;
    }
    grid_barrier(++bar);

    if (blockIdx.x == 0 && warp == 0) {
        float t2 = 0.f;
        for (int i = lane; i < NBLK; i += 32) t2 += __ldcg(&g_costpart[i]);
#pragma unroll
        for (int off = 16; off; off >>= 1)
            t2 += __shfl_xor_sync(0xffffffffu, t2, off);
        if (lane == 0) out[0] = t2 * (1.0f / 16.0f);
    }
}

// ---------------------------------------------------------------------------
extern "C" void kernel_launch(void* const* d_in, const int* in_sizes, int n_in,
                              void* d_out, int out_size) {
    const float* X = (const float*)d_in[0];   // output [16,1024,32]
    const float* Y = (const float*)d_in[1];   // labels [16,1024,32]

    dim3 cgrid(32, 32, 16);
    compute_C_kernel<<<cgrid, 256>>>(X, Y);

    sinkhorn_kernel<<<NBLK, NTHR>>>((float*)d_out);
}

// round 6
// speedup vs baseline: 3.0318x; 1.1507x over previous
#include <cuda_runtime.h>

// ---------------------------------------------------------------------------
// Sinkhorn (Wasserstein) loss, B=16, N=M=1024, D=32, EPS=1e-3, THRESH=0.1
// Round 5: occupancy 2 blocks/SM (256 blocks x 512 thr, launch_bounds(512,2)
// -> regs<=64 guaranteed, co-residency for the grid barrier guaranteed),
// CHUNK=64 (exact tiling), u-pass re-load sum phase (no 32-reg Xv cache),
// slimmed single-exp VUP on the v-pass.
// ---------------------------------------------------------------------------

#define BB    16
#define NN    1024
#define NBLK  256            // 16 row-chunk blocks per batch * 16 batches
#define RPB   16             // blocks per batch
#define NTHR  512
#define NWARP 16
#define CHUNK 64             // rows per chunk; 16*64 = 1024 exactly

// EPS * log(1/1024 + 1e-8)
#define K_EPSLOGMU  (-6.9314616e-3f)
// log2(e) / EPS
#define K_L2E_EPS   (1442.6950409f)
// exp cutoff: terms below 2^-46 of the max are dropped
#define K_CUT       (-0.032f)

__device__ float  g_C[16u * 1024u * 1024u];     // C[b][i][j]
__device__ float2 g_part[2][NBLK * 1024];       // (m,s) per (block,col), parity
__device__ float  g_errpart[2][NBLK];
__device__ float  g_costpart[NBLK];
__device__ unsigned g_count;
__device__ unsigned g_release;

// ---------------------------------------------------------------------------
// C[b][i][j] = sum_d (x[b][i][d] - y[b][j][d])^2 ; 32x32 output tile per block
// Block (0,0,0) thread 0 also resets the grid-barrier counters for this launch.
__global__ void compute_C_kernel(const float* __restrict__ X,
                                 const float* __restrict__ Y) {
    __shared__ float xs[32][33];
    __shared__ float ys[32][33];
    int b  = blockIdx.z;
    int i0 = blockIdx.y * 32;
    int j0 = blockIdx.x * 32;
    int tid = threadIdx.x;

    if (blockIdx.x == 0 && blockIdx.y == 0 && blockIdx.z == 0 && tid == 0) {
        g_count = 0u; g_release = 0u;
    }

    const float* xp = X + ((size_t)(b * NN + i0)) * 32;
    const float* yp = Y + ((size_t)(b * NN + j0)) * 32;
    for (int idx = tid; idx < 1024; idx += 256) {
        xs[idx >> 5][idx & 31] = xp[idx];
        ys[idx >> 5][idx & 31] = yp[idx];
    }
    __syncthreads();

    int tx = tid & 31;
    int ty = tid >> 5;
    float a0 = 0.f, a1 = 0.f, a2 = 0.f, a3 = 0.f;
#pragma unroll
    for (int d = 0; d < 32; d++) {
        float yv = ys[tx][d];
        float d0 = xs[ty][d]      - yv; a0 += d0 * d0;
        float d1 = xs[ty +  8][d] - yv; a1 += d1 * d1;
        float d2 = xs[ty + 16][d] - yv; a2 += d2 * d2;
        float d3 = xs[ty + 24][d] - yv; a3 += d3 * d3;
    }
    size_t base = ((size_t)b << 20);
    g_C[base + ((size_t)(i0 + ty)      << 10) + j0 + tx] = a0;
    g_C[base + ((size_t)(i0 + ty +  8) << 10) + j0 + tx] = a1;
    g_C[base + ((size_t)(i0 + ty + 16) << 10) + j0 + tx] = a2;
    g_C[base + ((size_t)(i0 + ty + 24) << 10) + j0 + tx] = a3;
}

// ---------------------------------------------------------------------------
// Grid barrier. 256 blocks, 2 co-resident per SM (guaranteed by
// launch_bounds(512,2): regs<=64, smem ~5KB) -> no deadlock.
__device__ __forceinline__ void grid_barrier(unsigned target) {
    __syncthreads();
    if (threadIdx.x == 0) {
        __threadfence();
        if (atomicAdd(&g_count, 1u) == NBLK - 1u) {
            g_count = 0u;
            __threadfence();
            atomicAdd(&g_release, 1u);
        } else {
            while (*((volatile unsigned*)&g_release) < target) { __nanosleep(32); }
        }
        __threadfence();
    }
    __syncthreads();
}

// slim online (m,s) update: single predicated exp2 path
#define VUPS(mm, ss, xx) do {                                                 \
    float x_  = (xx);                                                         \
    float hi_ = fmaxf(mm, x_);                                                \
    float lo_ = fminf(mm, x_);                                                \
    float d_  = lo_ - hi_;                                                    \
    float e_  = (d_ >= K_CUT) ? exp2f(d_ * K_L2E_EPS) : 0.f;                  \
    ss = (x_ > (mm)) ? fmaf(ss, e_, 1.f) : (ss + e_);                         \
    mm = hi_;                                                                 \
} while (0)

// combine a partial (pm, ps) into running (M, S)
#define PCOMB(M, S, pm, ps) do {                                              \
    if ((pm) > (M)) {                                                         \
        float d_ = (M) - (pm);                                                \
        (S) = (S) * ((d_ >= K_CUT) ? exp2f(d_ * K_L2E_EPS) : 0.f) + (ps);     \
        (M) = (pm);                                                           \
    } else {                                                                  \
        float d_ = (pm) - (M);                                                \
        if (d_ >= K_CUT) (S) += (ps) * exp2f(d_ * K_L2E_EPS);                 \
    }                                                                         \
} while (0)

// ---------------------------------------------------------------------------
__global__ __launch_bounds__(NTHR, 2) void sinkhorn_kernel(float* __restrict__ out) {
    __shared__ __align__(16) float s_v[1024];
    __shared__ float s_u[CHUNK];
    __shared__ float s_red[NWARP];
    __shared__ float s_bcast;

    int tid  = threadIdx.x;
    int lane = tid & 31;
    int warp = tid >> 5;
    int b    = blockIdx.x >> 4;        // / RPB
    int r    = blockIdx.x & 15;        // % RPB
    int row0 = r * CHUNK;
    const float* Cb = g_C + ((size_t)b << 20);
    const float4* sv4 = (const float4*)s_v;
    unsigned bar = 0;
    int p = 0;

    if (tid < CHUNK) s_u[tid] = 0.f;   // u0 = 0 (synced before first use below)

    for (int iter = 0; iter < 100; iter++) {
        p = iter & 1;
        // ---- combine v partials (written to buffer p^1 last iteration) ----
        if (iter == 0) {
            for (int j = tid; j < 1024; j += NTHR) s_v[j] = 0.f;
        } else {
            const float2* gp = g_part[p ^ 1];
            for (int j = tid; j < 1024; j += NTHR) {
                float M = -3.0e38f, S = 0.f;
#pragma unroll
                for (int rr = 0; rr < RPB; rr++) {
                    float2 q = __ldcg(&gp[((b << 4) + rr) * 1024 + j]);
                    PCOMB(M, S, q.x, q.y);
                }
                s_v[j] = K_EPSLOGMU - M - 1e-3f * __logf(S);
            }
        }
        __syncthreads();

        // ---- u pass: warp per row (4 rows/warp), row logsumexp of (v_j - C_ij)
        float e = 0.f;
#pragma unroll
        for (int q4 = 0; q4 < CHUNK / NWARP; q4++) {
            int idx = warp + q4 * NWARP;
            const float4* cr = (const float4*)(Cb + ((size_t)(row0 + idx) << 10));
            float ma = -3.0e38f, mb = -3.0e38f;
#pragma unroll
            for (int k = 0; k < 8; k += 2) {
                float4 c0 = cr[k * 32 + lane];
                float4 c1 = cr[(k + 1) * 32 + lane];
                float4 v0 = sv4[k * 32 + lane];
                float4 v1 = sv4[(k + 1) * 32 + lane];
                ma = fmaxf(ma, fmaxf(fmaxf(v0.x - c0.x, v0.y - c0.y),
                                     fmaxf(v0.z - c0.z, v0.w - c0.w)));
                mb = fmaxf(mb, fmaxf(fmaxf(v1.x - c1.x, v1.y - c1.y),
                                     fmaxf(v1.z - c1.z, v1.w - c1.w)));
            }
            float m = fmaxf(ma, mb);
            float lm = m;
#pragma unroll
            for (int off = 16; off; off >>= 1)
                m = fmaxf(m, __shfl_xor_sync(0xffffffffu, m, off));
            float s = 0.f;
            if (lm >= m + K_CUT) {      // few lanes; re-load row (L1 hit)
#pragma unroll
                for (int k = 0; k < 8; k++) {
                    float4 c = cr[k * 32 + lane];
                    float4 v = sv4[k * 32 + lane];
                    float t;
                    t = v.x - c.x - m; if (t >= K_CUT) s += exp2f(t * K_L2E_EPS);
                    t = v.y - c.y - m; if (t >= K_CUT) s += exp2f(t * K_L2E_EPS);
                    t = v.z - c.z - m; if (t >= K_CUT) s += exp2f(t * K_L2E_EPS);
                    t = v.w - c.w - m; if (t >= K_CUT) s += exp2f(t * K_L2E_EPS);
                }
            }
#pragma unroll
            for (int off = 16; off; off >>= 1)
                s += __shfl_xor_sync(0xffffffffu, s, off);
            if (lane == 0) {
                float nv = K_EPSLOGMU - m - 1e-3f * __logf(s);
                e += fabsf(nv - s_u[idx]);
                s_u[idx] = nv;
            }
        }
        if (lane == 0) s_red[warp] = e;
        __syncthreads();                    // s_u complete + s_red ready
        if (warp == 0) {
            float t2 = (lane < NWARP) ? s_red[lane] : 0.f;
#pragma unroll
            for (int off = 16; off; off >>= 1)
                t2 += __shfl_xor_sync(0xffffffffu, t2, off);
            if (lane == 0) g_errpart[p][blockIdx.x] = t2;
        }

        // ---- v pass: online column logsumexp of (u_i - C_ij); thread owns 2 cols
        {
            float m0 = -3.0e38f, s0 = 0.f, m1 = -3.0e38f, s1 = 0.f;
            const float2* cr2 = (const float2*)(Cb + ((size_t)row0 << 10));
#pragma unroll 2
            for (int idx = 0; idx < CHUNK; idx += 8) {
                float2 c0 = cr2[(size_t)(idx + 0) * 512 + tid];
                float2 c1 = cr2[(size_t)(idx + 1) * 512 + tid];
                float2 c2 = cr2[(size_t)(idx + 2) * 512 + tid];
                float2 c3 = cr2[(size_t)(idx + 3) * 512 + tid];
                float2 c4 = cr2[(size_t)(idx + 4) * 512 + tid];
                float2 c5 = cr2[(size_t)(idx + 5) * 512 + tid];
                float2 c6 = cr2[(size_t)(idx + 6) * 512 + tid];
                float2 c7 = cr2[(size_t)(idx + 7) * 512 + tid];
                float u0 = s_u[idx], u1 = s_u[idx + 1], u2 = s_u[idx + 2], u3 = s_u[idx + 3];
                float u4 = s_u[idx + 4], u5 = s_u[idx + 5], u6 = s_u[idx + 6], u7 = s_u[idx + 7];
                VUPS(m0, s0, u0 - c0.x); VUPS(m1, s1, u0 - c0.y);
                VUPS(m0, s0, u1 - c1.x); VUPS(m1, s1, u1 - c1.y);
                VUPS(m0, s0, u2 - c2.x); VUPS(m1, s1, u2 - c2.y);
                VUPS(m0, s0, u3 - c3.x); VUPS(m1, s1, u3 - c3.y);
                VUPS(m0, s0, u4 - c4.x); VUPS(m1, s1, u4 - c4.y);
                VUPS(m0, s0, u5 - c5.x); VUPS(m1, s1, u5 - c5.y);
                VUPS(m0, s0, u6 - c6.x); VUPS(m1, s1, u6 - c6.y);
                VUPS(m0, s0, u7 - c7.x); VUPS(m1, s1, u7 - c7.y);
            }
            // columns (2*tid, 2*tid+1) -> one float4 store into buffer p
            ((float4*)g_part[p])[blockIdx.x * 512 + tid] = make_float4(m0, s0, m1, s1);
        }

        grid_barrier(++bar);   // ONE barrier: err parts + v partials all visible

        // total err (deterministic fixed-order sum; identical in every block)
        if (warp == 0) {
            float t2 = 0.f;
            for (int i = lane; i < NBLK; i += 32) t2 += __ldcg(&g_errpart[p][i]);
#pragma unroll
            for (int off = 16; off; off >>= 1)
                t2 += __shfl_xor_sync(0xffffffffu, t2, off);
            if (lane == 0) s_bcast = t2;
        }
        __syncthreads();
        if (s_bcast * (1.0f / 16.0f) < 0.1f) break;
    }

    // ---- final v combine (from buffer p) + transport cost ----
    {
        const float2* gp = g_part[p];
        for (int j = tid; j < 1024; j += NTHR) {
            float M = -3.0e38f, S = 0.f;
#pragma unroll
            for (int rr = 0; rr < RPB; rr++) {
                float2 q = __ldcg(&gp[((b << 4) + rr) * 1024 + j]);
                PCOMB(M, S, q.x, q.y);
            }
            s_v[j] = K_EPSLOGMU - M - 1e-3f * __logf(S);
        }
    }
    __syncthreads();

    float acc = 0.f;
    for (int idx = warp; idx < CHUNK; idx += NWARP) {
        float ui = s_u[idx];
        const float4* cr = (const float4*)(Cb + ((size_t)(row0 + idx) << 10));
#pragma unroll
        for (int k = 0; k < 8; k++) {
            float4 c = cr[k * 32 + lane];
            float4 v = sv4[k * 32 + lane];
            float t;
            t = ui + v.x - c.x; if (t > -0.04f) acc += exp2f(t * K_L2E_EPS) * c.x;
            t = ui + v.y - c.y; if (t > -0.04f) acc += exp2f(t * K_L2E_EPS) * c.y;
            t = ui + v.z - c.z; if (t > -0.04f) acc += exp2f(t * K_L2E_EPS) * c.z;
            t = ui + v.w - c.w; if (t > -0.04f) acc += exp2f(t * K_L2E_EPS) * c.w;
        }
    }
#pragma unroll
    for (int off = 16; off; off >>= 1)
        acc += __shfl_xor_sync(0xffffffffu, acc, off);
    if (lane == 0) s_red[warp] = acc;
    __syncthreads();
    if (warp == 0) {
        float t2 = (lane < NWARP) ? s_red[lane] : 0.f;
#pragma unroll
        for (int off = 16; off; off >>= 1)
            t2 += __shfl_xor_sync(0xffffffffu, t2, off);
        if (lane == 0) g_costpart[blockIdx.x] = t2;
    }
    grid_barrier(++bar);

    if (blockIdx.x == 0 && warp == 0) {
        float t2 = 0.f;
        for (int i = lane; i < NBLK; i += 32) t2 += __ldcg(&g_costpart[i]);
#pragma unroll
        for (int off = 16; off; off >>= 1)
            t2 += __shfl_xor_sync(0xffffffffu, t2, off);
        if (lane == 0) out[0] = t2 * (1.0f / 16.0f);
    }
}

// ---------------------------------------------------------------------------
extern "C" void kernel_launch(void* const* d_in, const int* in_sizes, int n_in,
                              void* d_out, int out_size) {
    const float* X = (const float*)d_in[0];   // output [16,1024,32]
    const float* Y = (const float*)d_in[1];   // labels [16,1024,32]

    dim3 cgrid(32, 32, 16);
    compute_C_kernel<<<cgrid, 256>>>(X, Y);

    sinkhorn_kernel<<<NBLK, NTHR>>>((float*)d_out);
}

// round 7
// speedup vs baseline: 4.1481x; 1.3682x over previous
#include <cuda_runtime.h>

// ---------------------------------------------------------------------------
// Sinkhorn (Wasserstein) loss, B=16, N=M=1024, D=32, EPS=1e-3, THRESH=0.1
// Round 6: 288 blocks (18 per batch -> 97% SM fill at 2 blocks/SM),
// vote-gated chunked v-pass (skip chunks that provably contribute nothing:
// chunk_max < m + K_CUT < m), vote-gated u-pass sum phase, asm ex2.
// ---------------------------------------------------------------------------

#define BB    16
#define NN    1024
#define NBLK  288            // 18 row-chunk blocks per batch * 16 batches
#define RPB   18             // blocks per batch
#define NTHR  512
#define NWARP 16
#define CHUNK 57             // rows per chunk; last block gets 1024-17*57=55

// EPS * log(1/1024 + 1e-8)
#define K_EPSLOGMU  (-6.9314616e-3f)
// log2(e) / EPS
#define K_L2E_EPS   (1442.6950409f)
// exp cutoff: terms below 2^-46 of the max are dropped
#define K_CUT       (-0.032f)

__device__ float  g_C[16u * 1024u * 1024u];     // C[b][i][j]
__device__ float2 g_part[2][NBLK * 1024];       // (m,s) per (block,col), parity
__device__ float  g_errpart[2][NBLK];
__device__ float  g_costpart[NBLK];
__device__ unsigned g_count;
__device__ unsigned g_release;

__device__ __forceinline__ float ex2f(float x) {
    float r;
    asm("ex2.approx.ftz.f32 %0, %1;" : "=f"(r) : "f"(x));
    return r;
}

// ---------------------------------------------------------------------------
// C[b][i][j] = sum_d (x[b][i][d] - y[b][j][d])^2 ; 32x32 output tile per block
// Block (0,0,0) thread 0 also resets the grid-barrier counters for this launch.
__global__ void compute_C_kernel(const float* __restrict__ X,
                                 const float* __restrict__ Y) {
    __shared__ float xs[32][33];
    __shared__ float ys[32][33];
    int b  = blockIdx.z;
    int i0 = blockIdx.y * 32;
    int j0 = blockIdx.x * 32;
    int tid = threadIdx.x;

    if (blockIdx.x == 0 && blockIdx.y == 0 && blockIdx.z == 0 && tid == 0) {
        g_count = 0u; g_release = 0u;
    }

    const float* xp = X + ((size_t)(b * NN + i0)) * 32;
    const float* yp = Y + ((size_t)(b * NN + j0)) * 32;
    for (int idx = tid; idx < 1024; idx += 256) {
        xs[idx >> 5][idx & 31] = xp[idx];
        ys[idx >> 5][idx & 31] = yp[idx];
    }
    __syncthreads();

    int tx = tid & 31;
    int ty = tid >> 5;
    float a0 = 0.f, a1 = 0.f, a2 = 0.f, a3 = 0.f;
#pragma unroll
    for (int d = 0; d < 32; d++) {
        float yv = ys[tx][d];
        float d0 = xs[ty][d]      - yv; a0 += d0 * d0;
        float d1 = xs[ty +  8][d] - yv; a1 += d1 * d1;
        float d2 = xs[ty + 16][d] - yv; a2 += d2 * d2;
        float d3 = xs[ty + 24][d] - yv; a3 += d3 * d3;
    }
    size_t base = ((size_t)b << 20);
    g_C[base + ((size_t)(i0 + ty)      << 10) + j0 + tx] = a0;
    g_C[base + ((size_t)(i0 + ty +  8) << 10) + j0 + tx] = a1;
    g_C[base + ((size_t)(i0 + ty + 16) << 10) + j0 + tx] = a2;
    g_C[base + ((size_t)(i0 + ty + 24) << 10) + j0 + tx] = a3;
}

// ---------------------------------------------------------------------------
// Grid barrier. 288 blocks, 2 co-resident per SM guaranteed by
// launch_bounds(512,2) (regs<=64, smem ~5KB); 288 <= 296 -> single wave.
__device__ __forceinline__ void grid_barrier(unsigned target) {
    __syncthreads();
    if (threadIdx.x == 0) {
        __threadfence();
        if (atomicAdd(&g_count, 1u) == NBLK - 1u) {
            g_count = 0u;
            __threadfence();
            atomicAdd(&g_release, 1u);
        } else {
            while (*((volatile unsigned*)&g_release) < target) { __nanosleep(32); }
        }
        __threadfence();
    }
    __syncthreads();
}

// combine a partial (pm, ps) into running (M, S)
#define PCOMB(M, S, pm, ps) do {                                              \
    if ((pm) > (M)) {                                                         \
        float d_ = (M) - (pm);                                                \
        (S) = (S) * ((d_ >= K_CUT) ? ex2f(d_ * K_L2E_EPS) : 0.f) + (ps);      \
        (M) = (pm);                                                           \
    } else {                                                                  \
        float d_ = (pm) - (M);                                                \
        if (d_ >= K_CUT) (S) += (ps) * ex2f(d_ * K_L2E_EPS);                  \
    }                                                                         \
} while (0)

// ---------------------------------------------------------------------------
__global__ __launch_bounds__(NTHR, 2) void sinkhorn_kernel(float* __restrict__ out) {
    __shared__ __align__(16) float s_v[1024];
    __shared__ float s_u[64];
    __shared__ float s_red[NWARP];
    __shared__ float s_bcast;

    int tid  = threadIdx.x;
    int lane = tid & 31;
    int warp = tid >> 5;
    int b    = blockIdx.x / RPB;
    int r    = blockIdx.x % RPB;
    int row0 = r * CHUNK;
    int cnt  = (r == RPB - 1) ? (NN - row0) : CHUNK;
    const float* Cb = g_C + ((size_t)b << 20);
    const float4* sv4 = (const float4*)s_v;
    unsigned bar = 0;
    int p = 0;

    if (tid < 64) s_u[tid] = 0.f;      // u0 = 0 (synced before first use)

    for (int iter = 0; iter < 100; iter++) {
        p = iter & 1;
        // ---- combine v partials (written to buffer p^1 last iteration) ----
        if (iter == 0) {
            for (int j = tid; j < 1024; j += NTHR) s_v[j] = 0.f;
        } else {
            const float2* gp = g_part[p ^ 1];
            for (int j = tid; j < 1024; j += NTHR) {
                float M = -3.0e38f, S = 0.f;
#pragma unroll
                for (int rr = 0; rr < RPB; rr++) {
                    float2 q = __ldcg(&gp[(b * RPB + rr) * 1024 + j]);
                    PCOMB(M, S, q.x, q.y);
                }
                s_v[j] = K_EPSLOGMU - M - 1e-3f * __logf(S);
            }
        }
        __syncthreads();

        // ---- u pass: warp per row, row logsumexp of (v_j - C_ij) ----
        float e = 0.f;
        for (int idx = warp; idx < cnt; idx += NWARP) {
            const float4* cr = (const float4*)(Cb + ((size_t)(row0 + idx) << 10));
            float ma = -3.0e38f, mb = -3.0e38f;
#pragma unroll
            for (int k = 0; k < 8; k += 2) {
                float4 c0 = cr[k * 32 + lane];
                float4 c1 = cr[(k + 1) * 32 + lane];
                float4 v0 = sv4[k * 32 + lane];
                float4 v1 = sv4[(k + 1) * 32 + lane];
                ma = fmaxf(ma, fmaxf(fmaxf(v0.x - c0.x, v0.y - c0.y),
                                     fmaxf(v0.z - c0.z, v0.w - c0.w)));
                mb = fmaxf(mb, fmaxf(fmaxf(v1.x - c1.x, v1.y - c1.y),
                                     fmaxf(v1.z - c1.z, v1.w - c1.w)));
            }
            float m = fmaxf(ma, mb);
#pragma unroll
            for (int off = 16; off; off >>= 1)
                m = fmaxf(m, __shfl_xor_sync(0xffffffffu, m, off));
            float mk = m + K_CUT;
            float s = 0.f;
#pragma unroll
            for (int k = 0; k < 8; k++) {           // rows hot in L1
                float4 c = cr[k * 32 + lane];
                float4 v = sv4[k * 32 + lane];
                float x0 = v.x - c.x, x1 = v.y - c.y;
                float x2 = v.z - c.z, x3 = v.w - c.w;
                float mx = fmaxf(fmaxf(x0, x1), fmaxf(x2, x3));
                if (__any_sync(0xffffffffu, mx >= mk)) {
                    float t;
                    t = x0 - m; if (t >= K_CUT) s += ex2f(t * K_L2E_EPS);
                    t = x1 - m; if (t >= K_CUT) s += ex2f(t * K_L2E_EPS);
                    t = x2 - m; if (t >= K_CUT) s += ex2f(t * K_L2E_EPS);
                    t = x3 - m; if (t >= K_CUT) s += ex2f(t * K_L2E_EPS);
                }
            }
#pragma unroll
            for (int off = 16; off; off >>= 1)
                s += __shfl_xor_sync(0xffffffffu, s, off);
            if (lane == 0) {
                float nv = K_EPSLOGMU - m - 1e-3f * __logf(s);
                e += fabsf(nv - s_u[idx]);
                s_u[idx] = nv;
            }
        }
        if (lane == 0) s_red[warp] = e;
        __syncthreads();                    // s_u complete + s_red ready
        if (warp == 0) {
            float t2 = (lane < NWARP) ? s_red[lane] : 0.f;
#pragma unroll
            for (int off = 16; off; off >>= 1)
                t2 += __shfl_xor_sync(0xffffffffu, t2, off);
            if (lane == 0) g_errpart[p][blockIdx.x] = t2;
        }

        // ---- v pass: vote-gated chunked column logsumexp of (u_i - C_ij).
        // Thread owns cols (2*tid, 2*tid+1). Gate-false for a 4-row chunk
        // means chunk_max < m + K_CUT < m: body is provably a no-op, skip.
        {
            float m0 = -3.0e38f, s0 = 0.f, m1 = -3.0e38f, s1 = 0.f;
            const float2* cr2 = (const float2*)(Cb + ((size_t)row0 << 10));
            int idx = 0;
            for (; idx + 4 <= cnt; idx += 4) {
                float2 ca = cr2[(size_t)(idx + 0) * 512 + tid];
                float2 cb = cr2[(size_t)(idx + 1) * 512 + tid];
                float2 cc = cr2[(size_t)(idx + 2) * 512 + tid];
                float2 cd = cr2[(size_t)(idx + 3) * 512 + tid];
                float ua = s_u[idx], ub = s_u[idx + 1];
                float uc = s_u[idx + 2], ud = s_u[idx + 3];
                float x0a = ua - ca.x, x0b = ub - cb.x;
                float x0c = uc - cc.x, x0d = ud - cd.x;
                float x1a = ua - ca.y, x1b = ub - cb.y;
                float x1c = uc - cc.y, x1d = ud - cd.y;
                float cm0 = fmaxf(fmaxf(x0a, x0b), fmaxf(x0c, x0d));
                float cm1 = fmaxf(fmaxf(x1a, x1b), fmaxf(x1c, x1d));
                bool g = (cm0 >= m0 + K_CUT) || (cm1 >= m1 + K_CUT);
                if (__any_sync(0xffffffffu, g)) {
                    float n0 = fmaxf(m0, cm0);
                    float n1 = fmaxf(m1, cm1);
                    s0 *= ex2f((m0 - n0) * K_L2E_EPS);   // exact 1.0 when n0==m0
                    s1 *= ex2f((m1 - n1) * K_L2E_EPS);
                    float t;
                    t = x0a - n0; if (t >= K_CUT) s0 += ex2f(t * K_L2E_EPS);
                    t = x0b - n0; if (t >= K_CUT) s0 += ex2f(t * K_L2E_EPS);
                    t = x0c - n0; if (t >= K_CUT) s0 += ex2f(t * K_L2E_EPS);
                    t = x0d - n0; if (t >= K_CUT) s0 += ex2f(t * K_L2E_EPS);
                    t = x1a - n1; if (t >= K_CUT) s1 += ex2f(t * K_L2E_EPS);
                    t = x1b - n1; if (t >= K_CUT) s1 += ex2f(t * K_L2E_EPS);
                    t = x1c - n1; if (t >= K_CUT) s1 += ex2f(t * K_L2E_EPS);
                    t = x1d - n1; if (t >= K_CUT) s1 += ex2f(t * K_L2E_EPS);
                    m0 = n0; m1 = n1;
                }
            }
            for (; idx < cnt; idx++) {       // tail rows (1-3)
                float2 c = cr2[(size_t)idx * 512 + tid];
                float u0 = s_u[idx];
                float x0 = u0 - c.x, x1 = u0 - c.y;
                bool g = (x0 >= m0 + K_CUT) || (x1 >= m1 + K_CUT);
                if (__any_sync(0xffffffffu, g)) {
                    float n0 = fmaxf(m0, x0);
                    float n1 = fmaxf(m1, x1);
                    s0 *= ex2f((m0 - n0) * K_L2E_EPS);
                    s1 *= ex2f((m1 - n1) * K_L2E_EPS);
                    float t;
                    t = x0 - n0; if (t >= K_CUT) s0 += ex2f(t * K_L2E_EPS);
                    t = x1 - n1; if (t >= K_CUT) s1 += ex2f(t * K_L2E_EPS);
                    m0 = n0; m1 = n1;
                }
            }
            // columns (2*tid, 2*tid+1) -> one float4 store into buffer p
            ((float4*)g_part[p])[blockIdx.x * 512 + tid] = make_float4(m0, s0, m1, s1);
        }

        grid_barrier(++bar);   // ONE barrier: err parts + v partials all visible

        // total err (deterministic fixed-order sum; identical in every block)
        if (warp == 0) {
            float t2 = 0.f;
            for (int i = lane; i < NBLK; i += 32) t2 += __ldcg(&g_errpart[p][i]);
#pragma unroll
            for (int off = 16; off; off >>= 1)
                t2 += __shfl_xor_sync(0xffffffffu, t2, off);
            if (lane == 0) s_bcast = t2;
        }
        __syncthreads();
        if (s_bcast * (1.0f / 16.0f) < 0.1f) break;
    }

    // ---- final v combine (from buffer p) + transport cost ----
    {
        const float2* gp = g_part[p];
        for (int j = tid; j < 1024; j += NTHR) {
            float M = -3.0e38f, S = 0.f;
#pragma unroll
            for (int rr = 0; rr < RPB; rr++) {
                float2 q = __ldcg(&gp[(b * RPB + rr) * 1024 + j]);
                PCOMB(M, S, q.x, q.y);
            }
            s_v[j] = K_EPSLOGMU - M - 1e-3f * __logf(S);
        }
    }
    __syncthreads();

    float acc = 0.f;
    for (int idx = warp; idx < cnt; idx += NWARP) {
        float ui = s_u[idx];
        const float4* cr = (const float4*)(Cb + ((size_t)(row0 + idx) << 10));
#pragma unroll
        for (int k = 0; k < 8; k++) {
            float4 c = cr[k * 32 + lane];
            float4 v = sv4[k * 32 + lane];
            float t;
            t = ui + v.x - c.x; if (t > -0.04f) acc += ex2f(t * K_L2E_EPS) * c.x;
            t = ui + v.y - c.y; if (t > -0.04f) acc += ex2f(t * K_L2E_EPS) * c.y;
            t = ui + v.z - c.z; if (t > -0.04f) acc += ex2f(t * K_L2E_EPS) * c.z;
            t = ui + v.w - c.w; if (t > -0.04f) acc += ex2f(t * K_L2E_EPS) * c.w;
        }
    }
#pragma unroll
    for (int off = 16; off; off >>= 1)
        acc += __shfl_xor_sync(0xffffffffu, acc, off);
    if (lane == 0) s_red[warp] = acc;
    __syncthreads();
    if (warp == 0) {
        float t2 = (lane < NWARP) ? s_red[lane] : 0.f;
#pragma unroll
        for (int off = 16; off; off >>= 1)
            t2 += __shfl_xor_sync(0xffffffffu, t2, off);
        if (lane == 0) g_costpart[blockIdx.x] = t2;
    }
    grid_barrier(++bar);

    if (blockIdx.x == 0 && warp == 0) {
        float t2 = 0.f;
        for (int i = lane; i < NBLK; i += 32) t2 += __ldcg(&g_costpart[i]);
#pragma unroll
        for (int off = 16; off; off >>= 1)
            t2 += __shfl_xor_sync(0xffffffffu, t2, off);
        if (lane == 0) out[0] = t2 * (1.0f / 16.0f);
    }
}

// ---------------------------------------------------------------------------
extern "C" void kernel_launch(void* const* d_in, const int* in_sizes, int n_in,
                              void* d_out, int out_size) {
    const float* X = (const float*)d_in[0];   // output [16,1024,32]
    const float* Y = (const float*)d_in[1];   // labels [16,1024,32]

    dim3 cgrid(32, 32, 16);
    compute_C_kernel<<<cgrid, 256>>>(X, Y);

    sinkhorn_kernel<<<NBLK, NTHR>>>((float*)d_out);
}